// round 11
// baseline (speedup 1.0000x reference)
#include <cuda_runtime.h>
#include <cstdint>

// PeakAligner: L=220, window=[57,87); start=index_max-57 in [0,29]
//   in_bounds <=> start<=28; ss=min(start,28)
//   valid <=> p[57]==max(p[0..191]) && max(p[0..56]) < that max && in_bounds, p=row+ss
//   out[row][i] = valid ? p[3i] : 0 (i=0..63); mask[row] = !valid
//
// Two-pass + smem pipeline: pass1 (window LDG -> ss) issued 2-3 tiles ahead;
// pass2 cp.asyncs only the aligned 196-float span [ss&~3, +196) per row
// (800 B DRAM/row instead of 880). R4-style compute from smem.

#define L_DIM 220
#define WIN_LEN 30
#define WIN_LO 57
#define MAX_START 28
#define ROWS_PER_TILE 8
#define TILES_PER_BLOCK 8
#define NBUF 4
#define ROW_PAD 200            // padded smem row (floats); span needs <=196
#define THREADS 256

__device__ __forceinline__ unsigned ford(float f) {
    unsigned u = __float_as_uint(f);
    return u ^ (unsigned)(((int)u >> 31) | 0x80000000);
}
__device__ __forceinline__ float unford(unsigned t) {
    unsigned u = (t & 0x80000000u) ? (t ^ 0x80000000u) : ~t;
    return __uint_as_float(u);
}

__device__ __forceinline__ unsigned load_wu(const float* __restrict__ in,
                                            long long row, int lane, int K) {
    unsigned wu = 0u;
    if (row < K && lane < WIN_LEN)
        wu = ford(__ldg(in + row * L_DIM + WIN_LO + lane));
    return wu;
}

__device__ __forceinline__ void reduce_ss(unsigned wu, int& ss, bool& inb) {
    const unsigned wmax = __reduce_max_sync(0xffffffffu, wu);
    const unsigned wb   = __ballot_sync(0xffffffffu, wu == wmax);
    const int start = __ffs(wb) - 1;
    inb = (start <= MAX_START);
    ss  = min(start, MAX_START);
}

// Warp w copies its own row's aligned span [a, a+4*n4) into its smem slot.
// Every thread executes exactly one commit_group per call (uniform counting).
__device__ __forceinline__ void issue_x(float* sbuf, const float* __restrict__ in,
                                        long long row, int ss, int lane, int w, int K) {
    if (row < K) {
        const int a  = ss & ~3;                         // 16B-aligned span start
        const int n4 = min(49, (L_DIM - a) >> 2);       // 49 normally, 48 @ a=28
        const float4* src = reinterpret_cast<const float4*>(in + row * L_DIM + a);
        float4* dst = reinterpret_cast<float4*>(sbuf + w * ROW_PAD);
        if (lane < n4) {
            uint32_t d0 = (uint32_t)__cvta_generic_to_shared(dst + lane);
            asm volatile("cp.async.cg.shared.global [%0], [%1], 16;\n"
                         :: "r"(d0), "l"(src + lane));
        }
        if (lane + 32 < n4) {
            uint32_t d1 = (uint32_t)__cvta_generic_to_shared(dst + lane + 32);
            asm volatile("cp.async.cg.shared.global [%0], [%1], 16;\n"
                         :: "r"(d1), "l"(src + lane + 32));
        }
    }
    asm volatile("cp.async.commit_group;\n");
}

__device__ __forceinline__ void do_compute(const float* sbuf, int w, int lane,
                                           int ss, bool inb, long long row, int K,
                                           float* __restrict__ out,
                                           float* __restrict__ mask_out) {
    if (row >= K) return;
    const float* p = sbuf + w * ROW_PAD + (ss & 3);     // p[i] == gmem row[ss+i]

    const float x0 = p[lane];
    const float x1 = p[lane + 32];
    const float x2 = p[lane + 64];
    const float x3 = p[lane + 96];
    const float x4 = p[lane + 128];
    const float x5 = p[lane + 160];
    const float Ml = fmaxf(fmaxf(fmaxf(x0, x1), fmaxf(x2, x3)), fmaxf(x4, x5));
    const float Pl = (lane < 25) ? fmaxf(x0, x1) : x0;  // covers rel < 57
    const float M  = unford(__reduce_max_sync(0xffffffffu, ford(Ml)));
    const float P  = unford(__reduce_max_sync(0xffffffffu, ford(Pl)));
    const float v57 = p[57];
    const bool valid = (v57 == M) && (P < M) && inb;

    const float o0 = valid ? p[3 * lane]      : 0.0f;
    const float o1 = valid ? p[3 * lane + 96] : 0.0f;
    float* orow = out + (size_t)row * 64;
    __stcs(orow + lane,      o0);
    __stcs(orow + lane + 32, o1);
    if (lane == 0)
        __stcs(mask_out + row, valid ? 0.0f : 1.0f);    // removed_mask = !valid
}

__global__ __launch_bounds__(THREADS)
void peak_aligner_kernel(const float* __restrict__ in,
                         float* __restrict__ out,
                         float* __restrict__ mask_out,
                         int K, int total_tiles) {
    __shared__ float s[NBUF][ROWS_PER_TILE * ROW_PAD];  // 25600 B

    const int w    = threadIdx.x >> 5;
    const int lane = threadIdx.x & 31;

    const long long tile0 = (long long)blockIdx.x * TILES_PER_BLOCK;
    if (tile0 >= total_tiles) return;
    const int T = min(TILES_PER_BLOCK, (int)(total_tiles - tile0));

    #define ROWOF(t) ((tile0 + (t)) * ROWS_PER_TILE + w)

    int ss_c = 0, ss_n = 0, ss_n2 = 0;
    bool inb_c = false, inb_n = false, inb_n2 = false;
    unsigned wu = 0u;

    // ---- prologue: tiles 0,1 through both passes; window of tile 2 in flight ----
    reduce_ss(load_wu(in, ROWOF(0), lane, K), ss_c, inb_c);
    issue_x(s[0], in, ROWOF(0), ss_c, lane, w, K);
    if (T > 1) {
        reduce_ss(load_wu(in, ROWOF(1), lane, K), ss_n, inb_n);
        issue_x(s[1], in, ROWOF(1), ss_n, lane, w, K);
    }
    if (T > 2) wu = load_wu(in, ROWOF(2), lane, K);

    #pragma unroll 1
    for (int t = 0; t < T; t++) {
        if (t + 2 < T) {
            reduce_ss(wu, ss_n2, inb_n2);                       // wu loaded 1 iter ago
            issue_x(s[(t + 2) & 3], in, ROWOF(t + 2), ss_n2, lane, w, K);
            if (t + 3 < T) wu = load_wu(in, ROWOF(t + 3), lane, K);
            asm volatile("cp.async.wait_group 2;\n" ::: "memory");
        } else if (t + 1 < T) {
            asm volatile("cp.async.wait_group 1;\n" ::: "memory");
        } else {
            asm volatile("cp.async.wait_group 0;\n" ::: "memory");
        }
        __syncthreads();
        do_compute(s[t & 3], w, lane, ss_c, inb_c, ROWOF(t), K, out, mask_out);
        ss_c = ss_n; inb_c = inb_n;
        ss_n = ss_n2; inb_n = inb_n2;
    }
    #undef ROWOF
}

extern "C" void kernel_launch(void* const* d_in, const int* in_sizes, int n_in,
                              void* d_out, int out_size) {
    const float* in = (const float*)d_in[0];
    const int K = in_sizes[0] / L_DIM;
    float* out  = (float*)d_out;
    float* mask = out + (size_t)K * 64;
    const int total_tiles = (K + ROWS_PER_TILE - 1) / ROWS_PER_TILE;
    const int blocks = (total_tiles + TILES_PER_BLOCK - 1) / TILES_PER_BLOCK;
    peak_aligner_kernel<<<blocks, THREADS>>>(in, out, mask, K, total_tiles);
}

// round 12
// speedup vs baseline: 1.1186x; 1.1186x over previous
#include <cuda_runtime.h>
#include <cstdint>

// PeakAligner: L=220, window=[57,87); start=index_max-57 in [0,29]
//   in_bounds <=> start<=28; ss=min(start,28)
//   valid <=> p[57]==max(p[0..191]) && max(p[0..56]) < that max && in_bounds, p=row+ss
//   out[row][i] = valid ? p[3i] : 0 (i=0..63); mask[row] = !valid
//
// Warp-autonomous pipeline: each warp cp.asyncs its own rows into a private
// 4-deep smem ring and syncs only via its own per-thread wait_group state.
// ZERO block barriers -> no straggler coupling, smooth DRAM issue.

#define L_DIM 220
#define WIN_LEN 30
#define WIN_LO 57
#define MAX_START 28
#define WARPS 8
#define ROWS_PER_WARP 8            // block covers 64 rows
#define NBUF 4
#define THREADS 256
#define VEC4_PER_ROW (L_DIM / 4)   // 55

__device__ __forceinline__ unsigned ford(float f) {
    unsigned u = __float_as_uint(f);
    return u ^ (unsigned)(((int)u >> 31) | 0x80000000);
}
__device__ __forceinline__ float unford(unsigned t) {
    unsigned u = (t & 0x80000000u) ? (t ^ 0x80000000u) : ~t;
    return __uint_as_float(u);
}

// Warp-scope prefetch of one full row (880 B = 55 float4) into a private buffer.
// Uniform across the warp; every lane executes exactly one commit_group.
__device__ __forceinline__ void prefetch_row(float* buf, const float* __restrict__ in,
                                             long long row, int lane, int K) {
    if (row < K) {
        const float4* src = reinterpret_cast<const float4*>(in + row * L_DIM);
        float4* dst = reinterpret_cast<float4*>(buf);
        {
            uint32_t d = (uint32_t)__cvta_generic_to_shared(dst + lane);
            asm volatile("cp.async.cg.shared.global [%0], [%1], 16;\n"
                         :: "r"(d), "l"(src + lane));
        }
        if (lane < VEC4_PER_ROW - 32) {   // lanes 0..22
            uint32_t d = (uint32_t)__cvta_generic_to_shared(dst + lane + 32);
            asm volatile("cp.async.cg.shared.global [%0], [%1], 16;\n"
                         :: "r"(d), "l"(src + lane + 32));
        }
    }
    asm volatile("cp.async.commit_group;\n");
}

__device__ __forceinline__ void do_row(const float* r, long long row, int lane, int K,
                                       float* __restrict__ out,
                                       float* __restrict__ mask_out) {
    if (row >= K) return;

    // Step 1: first-argmax over window [57,87)
    const unsigned wu = (lane < WIN_LEN) ? ford(r[WIN_LO + lane]) : 0u;
    const unsigned wmax = __reduce_max_sync(0xffffffffu, wu);
    const unsigned wb   = __ballot_sync(0xffffffffu, wu == wmax);
    const int start = __ffs(wb) - 1;
    const bool in_bounds = (start <= MAX_START);
    const int ss = min(start, MAX_START);

    // Step 2: valid <=> v57==M(0..191) && P(0..56)<M
    const float* p = r + ss;
    const float x0 = p[lane];
    const float x1 = p[lane + 32];
    const float x2 = p[lane + 64];
    const float x3 = p[lane + 96];
    const float x4 = p[lane + 128];
    const float x5 = p[lane + 160];
    const float Ml = fmaxf(fmaxf(fmaxf(x0, x1), fmaxf(x2, x3)), fmaxf(x4, x5));
    const float Pl = (lane < 25) ? fmaxf(x0, x1) : x0;
    const float M  = unford(__reduce_max_sync(0xffffffffu, ford(Ml)));
    const float P  = unford(__reduce_max_sync(0xffffffffu, ford(Pl)));
    const float v57 = p[57];
    const bool valid = (v57 == M) && (P < M) && in_bounds;

    // Step 3: downsample + mask (streaming stores)
    const float o0 = valid ? p[3 * lane]      : 0.0f;
    const float o1 = valid ? p[3 * lane + 96] : 0.0f;
    float* orow = out + (size_t)row * 64;
    __stcs(orow + lane,      o0);
    __stcs(orow + lane + 32, o1);
    if (lane == 0)
        __stcs(mask_out + row, valid ? 0.0f : 1.0f);   // removed_mask = !valid
}

__global__ __launch_bounds__(THREADS)
void peak_aligner_kernel(const float* __restrict__ in,
                         float* __restrict__ out,
                         float* __restrict__ mask_out,
                         int K) {
    // per-warp private ring: 4 buffers x 220 floats (880 B, 16B-aligned rows)
    __shared__ float s[WARPS][NBUF][L_DIM];            // 28160 B -> 8 blocks/SM

    const int w    = threadIdx.x >> 5;
    const int lane = threadIdx.x & 31;

    // warp w's rows: base + 8*t  (block covers 64 contiguous rows)
    const long long base = (long long)blockIdx.x * (WARPS * ROWS_PER_WARP) + w;
    if (base >= K) return;

    // prologue: prime 3 buffers (distance-3 pipeline)
    prefetch_row(s[w][0], in, base,      lane, K);
    prefetch_row(s[w][1], in, base + 8,  lane, K);
    prefetch_row(s[w][2], in, base + 16, lane, K);

    #pragma unroll 1
    for (int t = 0; t < ROWS_PER_WARP; t++) {
        if (t + 3 < ROWS_PER_WARP) {
            prefetch_row(s[w][(t + 3) & 3], in, base + 8LL * (t + 3), lane, K);
            asm volatile("cp.async.wait_group 3;\n" ::: "memory");
        } else if (t + 2 < ROWS_PER_WARP) {
            asm volatile("cp.async.wait_group 2;\n" ::: "memory");
        } else if (t + 1 < ROWS_PER_WARP) {
            asm volatile("cp.async.wait_group 1;\n" ::: "memory");
        } else {
            asm volatile("cp.async.wait_group 0;\n" ::: "memory");
        }
        __syncwarp();
        do_row(s[w][t & 3], base + 8LL * t, lane, K, out, mask_out);
    }
}

extern "C" void kernel_launch(void* const* d_in, const int* in_sizes, int n_in,
                              void* d_out, int out_size) {
    const float* in = (const float*)d_in[0];
    const int K = in_sizes[0] / L_DIM;
    float* out  = (float*)d_out;
    float* mask = out + (size_t)K * 64;
    const int rows_per_block = WARPS * ROWS_PER_WARP;  // 64
    const int blocks = (K + rows_per_block - 1) / rows_per_block;
    peak_aligner_kernel<<<blocks, THREADS>>>(in, out, mask, K);
}

// round 13
// speedup vs baseline: 1.1940x; 1.0674x over previous
#include <cuda_runtime.h>
#include <cstdint>

// PeakAligner: L=220, window=[57,87); start=index_max-57 in [0,29]
//   in_bounds <=> start<=28; ss=min(start,28)
//   valid <=> p[57]==max(p[0..191]) && max(p[0..56]) < that max && in_bounds, p=row+ss
//   out[row][i] = valid ? p[3i] : 0 (i=0..63); mask[row] = !valid
//
// Champion family: block-cooperative smem pipeline, 8 tiles/block, NBUF=3,
// prefetch distance 2 (highest measured DRAM%), with per-tile ALU trimmed.

#define L_DIM 220
#define WIN_LEN 30
#define WIN_LO 57
#define MAX_START 28
#define ROWS_PER_TILE 8
#define TILES_PER_BLOCK 8
#define NBUF 3
#define THREADS 256
#define FLOATS_PER_TILE (ROWS_PER_TILE * L_DIM)   // 1760

__device__ __forceinline__ unsigned ford(float f) {
    unsigned u = __float_as_uint(f);
    return u ^ (unsigned)(((int)u >> 31) | 0x80000000);
}
__device__ __forceinline__ float unford(unsigned t) {
    unsigned u = (t & 0x80000000u) ? (t ^ 0x80000000u) : ~t;
    return __uint_as_float(u);
}

__device__ __forceinline__ void prefetch_tile(float* sbuf, const float* __restrict__ in,
                                              long long row0, int K) {
    const int rows_here = min(ROWS_PER_TILE, K - (int)row0);
    const float4* gin = reinterpret_cast<const float4*>(in + row0 * L_DIM);
    const int total4 = rows_here * (L_DIM / 4);
    int i = threadIdx.x;
    if (i < total4) {
        uint32_t sa = (uint32_t)__cvta_generic_to_shared(reinterpret_cast<float4*>(sbuf) + i);
        asm volatile("cp.async.cg.shared.global [%0], [%1], 16;\n" :: "r"(sa), "l"(gin + i));
    }
    i += THREADS;
    if (i < total4) {
        uint32_t sa = (uint32_t)__cvta_generic_to_shared(reinterpret_cast<float4*>(sbuf) + i);
        asm volatile("cp.async.cg.shared.global [%0], [%1], 16;\n" :: "r"(sa), "l"(gin + i));
    }
    asm volatile("cp.async.commit_group;\n");
}

__global__ __launch_bounds__(THREADS)
void peak_aligner_kernel(const float* __restrict__ in,
                         float* __restrict__ out,
                         float* __restrict__ mask_out,
                         int K, int total_tiles) {
    __shared__ float s[NBUF][FLOATS_PER_TILE];    // 21120 B -> 8 blocks/SM

    const int w    = threadIdx.x >> 5;
    const int lane = threadIdx.x & 31;

    const int tile0 = blockIdx.x * TILES_PER_BLOCK;
    if (tile0 >= total_tiles) return;
    const int T = min(TILES_PER_BLOCK, total_tiles - tile0);
    const long long row_base = (long long)tile0 * ROWS_PER_TILE;

    // prime pipeline: prefetch tiles 0 and 1 (distance 2)
    prefetch_tile(s[0], in, row_base, K);
    if (1 < T) prefetch_tile(s[1], in, row_base + ROWS_PER_TILE, K);

    int buf = 0;
    #pragma unroll 1
    for (int t = 0; t < T; t++) {
        if (t + 2 < T) {
            int pbuf = buf + 2; if (pbuf >= NBUF) pbuf -= NBUF;
            prefetch_tile(s[pbuf], in, row_base + (long long)(t + 2) * ROWS_PER_TILE, K);
            asm volatile("cp.async.wait_group 2;\n" ::: "memory");
        } else if (t + 1 < T) {
            asm volatile("cp.async.wait_group 1;\n" ::: "memory");
        } else {
            asm volatile("cp.async.wait_group 0;\n" ::: "memory");
        }
        __syncthreads();

        const long long row = row_base + (long long)t * ROWS_PER_TILE + w;
        if (row < K) {
            const float* r = s[buf] + w * L_DIM;

            // Step 1: first-argmax over window [57,87)
            const unsigned wu = (lane < WIN_LEN) ? ford(r[WIN_LO + lane]) : 0u;
            const unsigned wmax = __reduce_max_sync(0xffffffffu, wu);
            const unsigned wb = __ballot_sync(0xffffffffu, wu == wmax);
            const int start = __ffs(wb) - 1;
            const bool in_bounds = (start <= MAX_START);
            const int ss = min(start, MAX_START);

            // Step 2: valid <=> v57==M(0..191) && P(0..56)<M
            const float* p = r + ss;
            const float x0 = p[lane];
            const float x1 = p[lane + 32];
            const float x2 = p[lane + 64];
            const float x3 = p[lane + 96];
            const float x4 = p[lane + 128];
            const float x5 = p[lane + 160];
            const float Ml = fmaxf(fmaxf(fmaxf(x0, x1), fmaxf(x2, x3)), fmaxf(x4, x5));
            const float Pl = (lane < 25) ? fmaxf(x0, x1) : x0;
            const float M = unford(__reduce_max_sync(0xffffffffu, ford(Ml)));
            const float P = unford(__reduce_max_sync(0xffffffffu, ford(Pl)));
            const float v57 = __shfl_sync(0xffffffffu, x1, 25);   // p[57] (57=32+25)
            const bool valid = (v57 == M) && (P < M) && in_bounds;

            // Step 3: downsample + mask (streaming stores)
            const float o0 = valid ? p[3 * lane]      : 0.0f;
            const float o1 = valid ? p[3 * lane + 96] : 0.0f;
            float* orow = out + (size_t)row * 64;
            __stcs(orow + lane,      o0);
            __stcs(orow + lane + 32, o1);
            if (lane == 0)
                __stcs(mask_out + row, valid ? 0.0f : 1.0f);      // removed_mask = !valid
        }
        __syncthreads();   // everyone done with s[buf] before it is refilled
        buf = (buf + 1 == NBUF) ? 0 : buf + 1;
    }
}

extern "C" void kernel_launch(void* const* d_in, const int* in_sizes, int n_in,
                              void* d_out, int out_size) {
    const float* in = (const float*)d_in[0];
    const int K = in_sizes[0] / L_DIM;
    float* out  = (float*)d_out;
    float* mask = out + (size_t)K * 64;
    const int total_tiles = (K + ROWS_PER_TILE - 1) / ROWS_PER_TILE;
    const int blocks = (total_tiles + TILES_PER_BLOCK - 1) / TILES_PER_BLOCK;
    peak_aligner_kernel<<<blocks, THREADS>>>(in, out, mask, K, total_tiles);
}